// round 15
// baseline (speedup 1.0000x reference)
#include <cuda_runtime.h>
#include <cuda_fp16.h>
#include <mma.h>
#include <cstdint>

using namespace nvcuda;

#define HID   1024
#define BATCH 64
#define SEQ   256
#define NGATE 4096
#define NCTA  128
#define WHH_LD 1032
#define HA_LD 136
#define MB 32
#define CHB (32 * HA_LD)            // one chunk: 32 b x 136 halfs
#define HALF_BYTES (4 * CHB * 2)    // 34816 B: half of the per-bg B-image
#define HG_LD 66
#define HG_BLK (32 * HG_LD)

// lstm SMEM offsets (bytes)
#define OFF_CB  32
#define OFF_PS  288
#define OFF_CS  480
#define OFF_HG  2592
#define OFF_WHS 19488
#define OFF_HAS 151584
#define BSMEM   221216

__device__ float  g_xg[(size_t)BATCH * SEQ * NGATE];  // [b*SEQ+t][g*HID+k] fp32
__device__ __half g_xh[(size_t)BATCH * SEQ * HID];    // fp16 x
__device__ __half g_wxh[(size_t)NGATE * HID];         // fp16 Wx
__device__ __half g_whh[(size_t)NGATE * HID];         // fp16 Wh
// padded h ring: [slot][bg][kc][b][136]  (pre-padded SMEM image, bulk-copyable)
__device__ __half g_h2[4][2 * 8 * CHB];
__device__ int    g_cnt16[16];                        // [bg*8+grp]: 8 CTAs each

__device__ __forceinline__ void cp16(void* s, const void* g) {
    uint32_t sa = (uint32_t)__cvta_generic_to_shared(s);
    asm volatile("cp.async.cg.shared.global [%0], [%1], 16;\n" :: "r"(sa), "l"(g));
}
__device__ __forceinline__ void cp_commit() { asm volatile("cp.async.commit_group;\n"); }
template<int N> __device__ __forceinline__ void cp_wait() {
    asm volatile("cp.async.wait_group %0;\n" :: "n"(N));
}
__device__ __forceinline__ float sigm(float x) { return 1.0f / (1.0f + __expf(-x)); }
__device__ __forceinline__ int ld_relaxed(const int* p) {
    int v;
    asm volatile("ld.relaxed.gpu.global.s32 %0, [%1];" : "=r"(v) : "l"(p) : "memory");
    return v;
}
__device__ __forceinline__ void mbar_init(uint32_t mbar, uint32_t cnt) {
    asm volatile("mbarrier.init.shared.b64 [%0], %1;" :: "r"(mbar), "r"(cnt) : "memory");
}
__device__ __forceinline__ void mbar_expect_tx(uint32_t mbar, uint32_t tx) {
    asm volatile("mbarrier.arrive.expect_tx.shared.b64 _, [%0], %1;" :: "r"(mbar), "r"(tx) : "memory");
}
__device__ __forceinline__ void mbar_wait(uint32_t mbar, uint32_t parity) {
    asm volatile(
        "{\n\t.reg .pred P;\n"
        "WAIT_%=:\n\t"
        "mbarrier.try_wait.parity.acquire.cta.shared::cta.b64 P, [%0], %1, 0x989680;\n\t"
        "@P bra WAIT_DONE_%=;\n\t"
        "bra WAIT_%=;\n"
        "WAIT_DONE_%=:\n\t}"
        :: "r"(mbar), "r"(parity) : "memory");
}
__device__ __forceinline__ void bulk_ld(uint32_t dst, const void* src, uint32_t bytes, uint32_t mbar) {
    asm volatile(
        "cp.async.bulk.shared::cluster.global.mbarrier::complete_tx::bytes [%0], [%1], %2, [%3];"
        :: "r"(dst), "l"(src), "r"(bytes), "r"(mbar) : "memory");
}

// ------------------------------------------------------------------ convert to fp16
__global__ void convert_kernel(const float* __restrict__ x,
                               const float* __restrict__ Wx,
                               const float* __restrict__ Wh,
                               const float* __restrict__ h0) {
    size_t idx = (size_t)blockIdx.x * blockDim.x + threadIdx.x;
    size_t tot = (size_t)gridDim.x * blockDim.x;
    for (size_t i = idx; i < (size_t)BATCH * SEQ * HID; i += tot) g_xh[i]  = __float2half(x[i]);
    for (size_t i = idx; i < (size_t)NGATE * HID; i += tot)       g_wxh[i] = __float2half(Wx[i]);
    for (size_t i = idx; i < (size_t)NGATE * HID; i += tot)       g_whh[i] = __float2half(Wh[i]);
    for (size_t i = idx; i < (size_t)BATCH * HID; i += tot) {
        int b = (int)(i >> 10), k = (int)(i & 1023);
        g_h2[0][((b >> 5) * 8 + (k >> 7)) * CHB + (b & 31) * HA_LD + (k & 127)] = __float2half(h0[i]);
    }
}

// ------------------------------------------------------------------ phase A (fp16 wmma, 128x256 tiles)
#define BK 32
#define A_LD 40
#define ATM 128
#define ATN 256
#define ASMEM ((ATM + ATN) * A_LD * 2 * 3)   // 92160 B
__global__ void __launch_bounds__(512, 2) gemm_xg_kernel() {
    extern __shared__ __half smh[];
    __half* As = smh;                       // [3][128][40]
    __half* Bs = smh + 3 * ATM * A_LD;      // [3][256][40]
    const int tid = threadIdx.x;
    const int wid = tid >> 5;
    const int wm = wid & 3, wn = wid >> 2;  // M tile 0..3, N tile 0..3
    const int tm = blockIdx.y * ATM;
    const int tn = blockIdx.x * ATN;

    if (blockIdx.x == 0 && blockIdx.y == 0 && tid < 16) g_cnt16[tid] = 8;  // h(0) published

    wmma::fragment<wmma::accumulator, 16, 16, 16, float> acc[2][4];
    #pragma unroll
    for (int i = 0; i < 2; i++)
        #pragma unroll
        for (int j = 0; j < 4; j++) wmma::fill_fragment(acc[i][j], 0.0f);

    auto issue = [&](int kt) {
        int st = kt % 3;
        int kk = kt * BK;
        __half* a = As + st * ATM * A_LD;
        __half* b = Bs + st * ATN * A_LD;
        {
            int r = tid >> 2, sg = tid & 3;      // 128 rows x 4 segs = 512
            cp16(a + r * A_LD + sg * 8, g_xh + (size_t)(tm + r) * HID + kk + sg * 8);
        }
        #pragma unroll
        for (int i = 0; i < 2; i++) {
            int li = tid + i * 512;              // 256 rows x 4 segs = 1024
            int r = li >> 2, sg = li & 3;
            cp16(b + r * A_LD + sg * 8, g_wxh + (size_t)(tn + r) * HID + kk + sg * 8);
        }
    };
    issue(0); cp_commit();
    issue(1); cp_commit();

    for (int kt = 0; kt < HID / BK; kt++) {
        cp_wait<1>();
        __syncthreads();
        const int st = kt % 3;
        const __half* a = As + st * ATM * A_LD;
        const __half* b = Bs + st * ATN * A_LD;
        #pragma unroll
        for (int ks = 0; ks < 2; ks++) {
            wmma::fragment<wmma::matrix_a, 16, 16, 16, __half, wmma::row_major> af[2];
            #pragma unroll
            for (int i = 0; i < 2; i++)
                wmma::load_matrix_sync(af[i], a + (wm * 32 + i * 16) * A_LD + ks * 16, A_LD);
            #pragma unroll
            for (int j = 0; j < 4; j++) {
                wmma::fragment<wmma::matrix_b, 16, 16, 16, __half, wmma::col_major> bf;
                wmma::load_matrix_sync(bf, b + (wn * 64 + j * 16) * A_LD + ks * 16, A_LD);
                wmma::mma_sync(acc[0][j], af[0], bf, acc[0][j]);
                wmma::mma_sync(acc[1][j], af[1], bf, acc[1][j]);
            }
        }
        if (kt + 2 < HID / BK) issue(kt + 2);
        cp_commit();
    }
    #pragma unroll
    for (int i = 0; i < 2; i++)
        #pragma unroll
        for (int j = 0; j < 4; j++) {
            size_t r = tm + wm * 32 + i * 16;
            size_t n = tn + wn * 64 + j * 16;
            wmma::store_matrix_sync(g_xg + r * NGATE + n, acc[i][j], NGATE, wmma::mem_row_major);
        }
}

// ------------------------------------------------------------------ phase B
// 2 bg x 64 channel blocks. CONCURRENT split-half wavefront: warp0-lane0 handles
// half 0 (groups 0-3), warp4-lane0 handles half 1 (groups 4-7) — detect+bulk in parallel.
// 16 warps = 2 batch-tiles x 2 K-streams x 4 row-tiles; one mbar_wait per warp per step.
__global__ void __launch_bounds__(512, 1) lstm_kernel(const float* __restrict__ c0,
                                                      const float* __restrict__ bx,
                                                      const float* __restrict__ bh,
                                                      const float* __restrict__ peep,
                                                      const float* __restrict__ bgate,
                                                      float* __restrict__ out) {
    extern __shared__ char smc[];
    float*  cb  = (float*)(smc + OFF_CB);         // 64
    float*  ps  = (float*)(smc + OFF_PS);         // 48
    float*  cS  = (float*)(smc + OFF_CS);         // [16][33]
    float*  hgS = (float*)(smc + OFF_HG);         // [2][32][66]
    __half* Whs = (__half*)(smc + OFF_WHS);       // [64][1032]
    __half* hAs = (__half*)(smc + OFF_HAS);       // [8][32][136] full B-image
    const uint32_t sbase = (uint32_t)__cvta_generic_to_shared(smc);
    const uint32_t hAs_u = sbase + OFF_HAS;

    const int tid = threadIdx.x;
    const int wid = tid >> 5;
    const int rt  = wid & 3;                      // Wh row tile 0..3
    const int sk  = (wid >> 2) & 1;               // K-stream 0..1 (half 0 / half 1)
    const int bt  = wid >> 3;                     // batch tile 0..1
    const int j   = blockIdx.x & 63;              // channel block
    const int bg  = blockIdx.x >> 6;              // batch group
    const int c0ch = j * 16;
    const int grp = bg * 8 + (j >> 3);

    // one-time: stage this CTA's fp16 Wh slice (64 rows x 1024)
    #pragma unroll
    for (int i = 0; i < 16; i++) {
        int li = tid + i * 512;
        int n = li >> 7, sg = li & 127;
        int g = n >> 4, ch = n & 15;
        cp16(Whs + n * WHH_LD + sg * 8,
             g_whh + ((size_t)(g * HID + c0ch + ch)) * HID + sg * 8);
    }
    cp_commit();
    if (tid < 64) {
        int g = tid >> 4, ch = tid & 15;
        cb[tid] = bx[g * HID + c0ch + ch] + bh[g * HID + c0ch + ch] + bgate[g * HID + c0ch + ch];
    }
    if (tid < 48) ps[tid] = peep[(tid >> 4) * HID + c0ch + (tid & 15)];
    {
        int b = tid >> 4, ch = tid & 15;
        cS[ch * 33 + b] = c0[(size_t)(bg * MB + b) * HID + c0ch + ch];
    }
    if (tid == 0) {
        mbar_init(sbase, 1);        // half 0
        mbar_init(sbase + 8, 1);    // half 1
        asm volatile("fence.proxy.async.shared::cta;" ::: "memory");
    }
    cp_wait<0>();
    __syncthreads();

    const int b  = tid >> 4;
    const int ch = tid & 15;
    const size_t gb = (size_t)(bg * MB + b);
    const uint32_t my_mbar = sbase + sk * 8;
    const bool is_poller = (tid == 0) || (tid == 128);   // warp0 / warp4 lane 0

    for (int t = 0; t < SEQ; t++) {
        // prefetch this step's input-gate preactivations (independent of h_t)
        const float* xr = g_xg + (gb * SEQ + t) * NGATE + c0ch + ch;
        float xi0 = __ldg(xr);
        float xi1 = __ldg(xr + HID);
        float xi2 = __ldg(xr + 2 * HID);
        float xi3 = __ldg(xr + 3 * HID);

        if (is_poller) {
            const int half = (tid == 128);
            const int need = 8 * (t + 1);
            const int* cnt = g_cnt16 + bg * 8 + half * 4;
            const __half* hsrc = g_h2[t & 3] + (size_t)bg * 8 * CHB;
            while (true) {
                int m = ld_relaxed(cnt);
                #pragma unroll
                for (int q = 1; q < 4; q++) { int v = ld_relaxed(cnt + q); m = v < m ? v : m; }
                if (m >= need) break;
            }
            asm volatile("fence.acq_rel.gpu;" ::: "memory");
            asm volatile("fence.proxy.async;" ::: "memory");
            mbar_expect_tx(sbase + half * 8, HALF_BYTES);
            bulk_ld(hAs_u + half * HALF_BYTES, hsrc + half * 4 * CHB, HALF_BYTES, sbase + half * 8);
        }

        // each warp waits only on its own half, then runs 32 uninterrupted iterations
        mbar_wait(my_mbar, t & 1);

        wmma::fragment<wmma::accumulator, 16, 16, 16, float> acc0, acc1;
        wmma::fill_fragment(acc0, 0.0f);
        wmma::fill_fragment(acc1, 0.0f);
        const __half* bbase = Whs + (rt * 16) * WHH_LD;
        #pragma unroll 8
        for (int f = sk * 32; f < sk * 32 + 32; f += 2) {
            const __half* a0 = hAs + (f >> 3) * CHB + (bt * 16) * HA_LD + (f & 7) * 16;
            const __half* a1 = hAs + ((f + 1) >> 3) * CHB + (bt * 16) * HA_LD + ((f + 1) & 7) * 16;
            wmma::fragment<wmma::matrix_a, 16, 16, 16, __half, wmma::row_major> af0, af1;
            wmma::fragment<wmma::matrix_b, 16, 16, 16, __half, wmma::col_major> bf0, bf1;
            wmma::load_matrix_sync(af0, a0, HA_LD);
            wmma::load_matrix_sync(bf0, bbase + f * 16, WHH_LD);
            wmma::load_matrix_sync(af1, a1, HA_LD);
            wmma::load_matrix_sync(bf1, bbase + (f + 1) * 16, WHH_LD);
            wmma::mma_sync(acc0, af0, bf0, acc0);
            wmma::mma_sync(acc1, af1, bf1, acc1);
        }
        #pragma unroll
        for (int e = 0; e < acc0.num_elements; e++) acc0.x[e] += acc1.x[e];
        wmma::store_matrix_sync(hgS + sk * HG_BLK + (bt * 16) * HG_LD + rt * 16,
                                acc0, HG_LD, wmma::mem_row_major);
        __syncthreads();

        // epilogue: sum 2 K-stream partials, gates; h written into ring image
        float c = cS[ch * 33 + b];
        const float* hb = hgS + b * HG_LD;
        float hv0 = hb[ch]      + hb[HG_BLK + ch];
        float hv1 = hb[16 + ch] + hb[HG_BLK + 16 + ch];
        float hv2 = hb[32 + ch] + hb[HG_BLK + 32 + ch];
        float hv3 = hb[48 + ch] + hb[HG_BLK + 48 + ch];
        float pi = xi0 + hv0 + ps[ch]      * c + cb[ch];
        float pf = xi1 + hv1 + ps[16 + ch] * c + cb[16 + ch];
        float pc = xi2 + hv2                   + cb[32 + ch];
        float po = xi3 + hv3                   + cb[48 + ch];
        float cn = sigm(pf) * c + sigm(pi) + tanhf(pc);
        float hn = sigm(po + ps[32 + ch] * cn) * tanhf(cn);
        cS[ch * 33 + b] = cn;
        g_h2[(t + 1) & 3][((size_t)bg * 8 + (j >> 3)) * CHB + b * HA_LD + (j & 7) * 16 + ch]
            = __float2half(hn);
        __syncthreads();                    // all h stores happen-before the release
        if (tid == 0)
            asm volatile("red.release.gpu.global.add.s32 [%0], %1;"
                         :: "l"(g_cnt16 + grp), "r"(1) : "memory");

        // out store AFTER release — off the critical handshake path
        out[(gb * SEQ + t) * HID + c0ch + ch] = hn;
    }
}

extern "C" void kernel_launch(void* const* d_in, const int* in_sizes, int n_in,
                              void* d_out, int out_size) {
    const float* x     = (const float*)d_in[0];
    const float* h0    = (const float*)d_in[1];
    const float* c0    = (const float*)d_in[2];
    const float* Wx    = (const float*)d_in[3];
    const float* bx    = (const float*)d_in[4];
    const float* Wh    = (const float*)d_in[5];
    const float* bh    = (const float*)d_in[6];
    const float* peep  = (const float*)d_in[7];
    const float* bgate = (const float*)d_in[8];
    float* out = (float*)d_out;

    cudaFuncSetAttribute(gemm_xg_kernel, cudaFuncAttributeMaxDynamicSharedMemorySize, ASMEM);
    cudaFuncSetAttribute(lstm_kernel, cudaFuncAttributeMaxDynamicSharedMemorySize, BSMEM);

    convert_kernel<<<1024, 256>>>(x, Wx, Wh, h0);
    gemm_xg_kernel<<<dim3(NGATE / ATN, BATCH * SEQ / ATM), 512, ASMEM>>>();
    lstm_kernel<<<NCTA, 512, BSMEM>>>(c0, bx, bh, peep, bgate, out);
}

// round 16
// speedup vs baseline: 1.5920x; 1.5920x over previous
#include <cuda_runtime.h>
#include <cuda_fp16.h>
#include <mma.h>
#include <cstdint>

using namespace nvcuda;

#define HID   1024
#define BATCH 64
#define SEQ   256
#define NGATE 4096
#define NCTA  128
#define WHH_LD 1032
#define HA_LD 136
#define MB 32
#define CHB (32 * HA_LD)            // one chunk: 32 b x 136 halfs
#define HALF_BYTES (4 * CHB * 2)    // 34816 B: half of the per-bg B-image
#define HG_LD 66
#define HG_BLK (32 * HG_LD)

// lstm SMEM offsets (bytes)
#define OFF_CB  32
#define OFF_PS  288
#define OFF_CS  480
#define OFF_HG  2592
#define OFF_WHS 19488
#define OFF_HAS 151584
#define BSMEM   221216

__device__ float  g_xg[(size_t)BATCH * SEQ * NGATE];  // [b*SEQ+t][g*HID+k] fp32
__device__ __half g_xh[(size_t)BATCH * SEQ * HID];    // fp16 x
__device__ __half g_wxh[(size_t)NGATE * HID];         // fp16 Wx
__device__ __half g_whh[(size_t)NGATE * HID];         // fp16 Wh
// padded h ring: [slot][bg][kc][b][136]  (pre-padded SMEM image, bulk-copyable)
__device__ __half g_h2[4][2 * 8 * CHB];
__device__ int    g_cnt16[16];                        // [bg*8+grp]: 8 CTAs each

__device__ __forceinline__ void cp16(void* s, const void* g) {
    uint32_t sa = (uint32_t)__cvta_generic_to_shared(s);
    asm volatile("cp.async.cg.shared.global [%0], [%1], 16;\n" :: "r"(sa), "l"(g));
}
__device__ __forceinline__ void cp_commit() { asm volatile("cp.async.commit_group;\n"); }
template<int N> __device__ __forceinline__ void cp_wait() {
    asm volatile("cp.async.wait_group %0;\n" :: "n"(N));
}
__device__ __forceinline__ float sigm(float x) { return 1.0f / (1.0f + __expf(-x)); }
__device__ __forceinline__ int ld_relaxed(const int* p) {
    int v;
    asm volatile("ld.relaxed.gpu.global.s32 %0, [%1];" : "=r"(v) : "l"(p) : "memory");
    return v;
}
__device__ __forceinline__ void mbar_init(uint32_t mbar, uint32_t cnt) {
    asm volatile("mbarrier.init.shared.b64 [%0], %1;" :: "r"(mbar), "r"(cnt) : "memory");
}
__device__ __forceinline__ void mbar_expect_tx(uint32_t mbar, uint32_t tx) {
    asm volatile("mbarrier.arrive.expect_tx.shared.b64 _, [%0], %1;" :: "r"(mbar), "r"(tx) : "memory");
}
__device__ __forceinline__ void mbar_wait(uint32_t mbar, uint32_t parity) {
    asm volatile(
        "{\n\t.reg .pred P;\n"
        "WAIT_%=:\n\t"
        "mbarrier.try_wait.parity.acquire.cta.shared::cta.b64 P, [%0], %1, 0x989680;\n\t"
        "@P bra WAIT_DONE_%=;\n\t"
        "bra WAIT_%=;\n"
        "WAIT_DONE_%=:\n\t}"
        :: "r"(mbar), "r"(parity) : "memory");
}
__device__ __forceinline__ void bulk_ld(uint32_t dst, const void* src, uint32_t bytes, uint32_t mbar) {
    asm volatile(
        "cp.async.bulk.shared::cluster.global.mbarrier::complete_tx::bytes [%0], [%1], %2, [%3];"
        :: "r"(dst), "l"(src), "r"(bytes), "r"(mbar) : "memory");
}

// ------------------------------------------------------------------ convert to fp16
__global__ void convert_kernel(const float* __restrict__ x,
                               const float* __restrict__ Wx,
                               const float* __restrict__ Wh,
                               const float* __restrict__ h0) {
    size_t idx = (size_t)blockIdx.x * blockDim.x + threadIdx.x;
    size_t tot = (size_t)gridDim.x * blockDim.x;
    for (size_t i = idx; i < (size_t)BATCH * SEQ * HID; i += tot) g_xh[i]  = __float2half(x[i]);
    for (size_t i = idx; i < (size_t)NGATE * HID; i += tot)       g_wxh[i] = __float2half(Wx[i]);
    for (size_t i = idx; i < (size_t)NGATE * HID; i += tot)       g_whh[i] = __float2half(Wh[i]);
    for (size_t i = idx; i < (size_t)BATCH * HID; i += tot) {
        int b = (int)(i >> 10), k = (int)(i & 1023);
        g_h2[0][((b >> 5) * 8 + (k >> 7)) * CHB + (b & 31) * HA_LD + (k & 127)] = __float2half(h0[i]);
    }
}

// ------------------------------------------------------------------ phase A (fp16 wmma, 128x128, 256 thr — proven config)
#define BK 32
#define A_LD 40
#define ASMEM (2 * 3 * 128 * A_LD * 2)
__global__ void __launch_bounds__(256, 2) gemm_xg_kernel() {
    extern __shared__ __half smh[];
    __half* As = smh;                     // [3][128][40]
    __half* Bs = smh + 3 * 128 * A_LD;    // [3][128][40]
    const int tid = threadIdx.x;
    const int wid = tid >> 5;
    const int wm = wid & 3, wn = wid >> 2;
    const int tm = blockIdx.y * 128;
    const int tn = blockIdx.x * 128;

    if (blockIdx.x == 0 && blockIdx.y == 0 && tid < 16) g_cnt16[tid] = 8;  // h(0) published

    wmma::fragment<wmma::accumulator, 16, 16, 16, float> acc[2][4];
    #pragma unroll
    for (int i = 0; i < 2; i++)
        #pragma unroll
        for (int j = 0; j < 4; j++) wmma::fill_fragment(acc[i][j], 0.0f);

    auto issue = [&](int kt) {
        int st = kt % 3;
        int kk = kt * BK;
        __half* a = As + st * 128 * A_LD;
        __half* b = Bs + st * 128 * A_LD;
        #pragma unroll
        for (int i = 0; i < 4; i++) {
            int li = tid + i * 256;
            int half_sel = li >> 9;
            int lj = li & 511;
            int r = lj >> 2, sg = lj & 3;
            if (half_sel == 0)
                cp16(a + r * A_LD + sg * 8, g_xh  + (size_t)(tm + r) * HID + kk + sg * 8);
            else
                cp16(b + r * A_LD + sg * 8, g_wxh + (size_t)(tn + r) * HID + kk + sg * 8);
        }
    };
    issue(0); cp_commit();
    issue(1); cp_commit();

    for (int kt = 0; kt < HID / BK; kt++) {
        cp_wait<1>();
        __syncthreads();
        const int st = kt % 3;
        const __half* a = As + st * 128 * A_LD;
        const __half* b = Bs + st * 128 * A_LD;
        #pragma unroll
        for (int ks = 0; ks < 2; ks++) {
            wmma::fragment<wmma::matrix_a, 16, 16, 16, __half, wmma::row_major> af[2];
            wmma::fragment<wmma::matrix_b, 16, 16, 16, __half, wmma::col_major> bf[4];
            #pragma unroll
            for (int i = 0; i < 2; i++)
                wmma::load_matrix_sync(af[i], a + (wm * 32 + i * 16) * A_LD + ks * 16, A_LD);
            #pragma unroll
            for (int j = 0; j < 4; j++)
                wmma::load_matrix_sync(bf[j], b + (wn * 64 + j * 16) * A_LD + ks * 16, A_LD);
            #pragma unroll
            for (int i = 0; i < 2; i++)
                #pragma unroll
                for (int j = 0; j < 4; j++)
                    wmma::mma_sync(acc[i][j], af[i], bf[j], acc[i][j]);
        }
        if (kt + 2 < HID / BK) issue(kt + 2);
        cp_commit();
    }
    #pragma unroll
    for (int i = 0; i < 2; i++)
        #pragma unroll
        for (int j = 0; j < 4; j++) {
            size_t r = tm + wm * 32 + i * 16;
            size_t n = tn + wn * 64 + j * 16;
            wmma::store_matrix_sync(g_xg + r * NGATE + n, acc[i][j], NGATE, wmma::mem_row_major);
        }
}

// ------------------------------------------------------------------ phase B
// 2 bg x 64 channel blocks. CONCURRENT split-half wavefront: warp0-lane0 handles
// half 0 (groups 0-3), warp4-lane0 handles half 1 (groups 4-7) — detect+bulk in parallel.
// 16 warps = 2 batch-tiles x 2 K-streams x 4 row-tiles; one mbar_wait per warp per step.
__global__ void __launch_bounds__(512, 1) lstm_kernel(const float* __restrict__ c0,
                                                      const float* __restrict__ bx,
                                                      const float* __restrict__ bh,
                                                      const float* __restrict__ peep,
                                                      const float* __restrict__ bgate,
                                                      float* __restrict__ out) {
    extern __shared__ char smc[];
    float*  cb  = (float*)(smc + OFF_CB);         // 64
    float*  ps  = (float*)(smc + OFF_PS);         // 48
    float*  cS  = (float*)(smc + OFF_CS);         // [16][33]
    float*  hgS = (float*)(smc + OFF_HG);         // [2][32][66]
    __half* Whs = (__half*)(smc + OFF_WHS);       // [64][1032]
    __half* hAs = (__half*)(smc + OFF_HAS);       // [8][32][136] full B-image
    const uint32_t sbase = (uint32_t)__cvta_generic_to_shared(smc);
    const uint32_t hAs_u = sbase + OFF_HAS;

    const int tid = threadIdx.x;
    const int wid = tid >> 5;
    const int rt  = wid & 3;                      // Wh row tile 0..3
    const int sk  = (wid >> 2) & 1;               // K-stream 0..1 (half 0 / half 1)
    const int bt  = wid >> 3;                     // batch tile 0..1
    const int j   = blockIdx.x & 63;              // channel block
    const int bg  = blockIdx.x >> 6;              // batch group
    const int c0ch = j * 16;
    const int grp = bg * 8 + (j >> 3);

    // one-time: stage this CTA's fp16 Wh slice (64 rows x 1024)
    #pragma unroll
    for (int i = 0; i < 16; i++) {
        int li = tid + i * 512;
        int n = li >> 7, sg = li & 127;
        int g = n >> 4, ch = n & 15;
        cp16(Whs + n * WHH_LD + sg * 8,
             g_whh + ((size_t)(g * HID + c0ch + ch)) * HID + sg * 8);
    }
    cp_commit();
    if (tid < 64) {
        int g = tid >> 4, ch = tid & 15;
        cb[tid] = bx[g * HID + c0ch + ch] + bh[g * HID + c0ch + ch] + bgate[g * HID + c0ch + ch];
    }
    if (tid < 48) ps[tid] = peep[(tid >> 4) * HID + c0ch + (tid & 15)];
    {
        int b = tid >> 4, ch = tid & 15;
        cS[ch * 33 + b] = c0[(size_t)(bg * MB + b) * HID + c0ch + ch];
    }
    if (tid == 0) {
        mbar_init(sbase, 1);        // half 0
        mbar_init(sbase + 8, 1);    // half 1
        asm volatile("fence.proxy.async.shared::cta;" ::: "memory");
    }
    cp_wait<0>();
    __syncthreads();

    const int b  = tid >> 4;
    const int ch = tid & 15;
    const size_t gb = (size_t)(bg * MB + b);
    const uint32_t my_mbar = sbase + sk * 8;
    const bool is_poller = (tid == 0) || (tid == 128);   // warp0 / warp4 lane 0

    for (int t = 0; t < SEQ; t++) {
        // prefetch this step's input-gate preactivations (independent of h_t)
        const float* xr = g_xg + (gb * SEQ + t) * NGATE + c0ch + ch;
        float xi0 = __ldg(xr);
        float xi1 = __ldg(xr + HID);
        float xi2 = __ldg(xr + 2 * HID);
        float xi3 = __ldg(xr + 3 * HID);

        if (is_poller) {
            const int half = (tid == 128);
            const int need = 8 * (t + 1);
            const int* cnt = g_cnt16 + bg * 8 + half * 4;
            const __half* hsrc = g_h2[t & 3] + (size_t)bg * 8 * CHB;
            while (true) {
                int m = ld_relaxed(cnt);
                #pragma unroll
                for (int q = 1; q < 4; q++) { int v = ld_relaxed(cnt + q); m = v < m ? v : m; }
                if (m >= need) break;
            }
            asm volatile("fence.acq_rel.gpu;" ::: "memory");
            asm volatile("fence.proxy.async;" ::: "memory");
            mbar_expect_tx(sbase + half * 8, HALF_BYTES);
            bulk_ld(hAs_u + half * HALF_BYTES, hsrc + half * 4 * CHB, HALF_BYTES, sbase + half * 8);
        }

        // each warp waits only on its own half, then runs 32 uninterrupted iterations
        mbar_wait(my_mbar, t & 1);

        wmma::fragment<wmma::accumulator, 16, 16, 16, float> acc0, acc1;
        wmma::fill_fragment(acc0, 0.0f);
        wmma::fill_fragment(acc1, 0.0f);
        const __half* bbase = Whs + (rt * 16) * WHH_LD;
        #pragma unroll 8
        for (int f = sk * 32; f < sk * 32 + 32; f += 2) {
            const __half* a0 = hAs + (f >> 3) * CHB + (bt * 16) * HA_LD + (f & 7) * 16;
            const __half* a1 = hAs + ((f + 1) >> 3) * CHB + (bt * 16) * HA_LD + ((f + 1) & 7) * 16;
            wmma::fragment<wmma::matrix_a, 16, 16, 16, __half, wmma::row_major> af0, af1;
            wmma::fragment<wmma::matrix_b, 16, 16, 16, __half, wmma::col_major> bf0, bf1;
            wmma::load_matrix_sync(af0, a0, HA_LD);
            wmma::load_matrix_sync(bf0, bbase + f * 16, WHH_LD);
            wmma::load_matrix_sync(af1, a1, HA_LD);
            wmma::load_matrix_sync(bf1, bbase + (f + 1) * 16, WHH_LD);
            wmma::mma_sync(acc0, af0, bf0, acc0);
            wmma::mma_sync(acc1, af1, bf1, acc1);
        }
        #pragma unroll
        for (int e = 0; e < acc0.num_elements; e++) acc0.x[e] += acc1.x[e];
        wmma::store_matrix_sync(hgS + sk * HG_BLK + (bt * 16) * HG_LD + rt * 16,
                                acc0, HG_LD, wmma::mem_row_major);
        __syncthreads();

        // epilogue: sum 2 K-stream partials, gates; h written into ring image
        float c = cS[ch * 33 + b];
        const float* hb = hgS + b * HG_LD;
        float hv0 = hb[ch]      + hb[HG_BLK + ch];
        float hv1 = hb[16 + ch] + hb[HG_BLK + 16 + ch];
        float hv2 = hb[32 + ch] + hb[HG_BLK + 32 + ch];
        float hv3 = hb[48 + ch] + hb[HG_BLK + 48 + ch];
        float pi = xi0 + hv0 + ps[ch]      * c + cb[ch];
        float pf = xi1 + hv1 + ps[16 + ch] * c + cb[16 + ch];
        float pc = xi2 + hv2                   + cb[32 + ch];
        float po = xi3 + hv3                   + cb[48 + ch];
        float cn = sigm(pf) * c + sigm(pi) + tanhf(pc);
        float hn = sigm(po + ps[32 + ch] * cn) * tanhf(cn);
        cS[ch * 33 + b] = cn;
        g_h2[(t + 1) & 3][((size_t)bg * 8 + (j >> 3)) * CHB + b * HA_LD + (j & 7) * 16 + ch]
            = __float2half(hn);
        __syncthreads();                    // all h stores happen-before the release
        if (tid == 0)
            asm volatile("red.release.gpu.global.add.s32 [%0], %1;"
                         :: "l"(g_cnt16 + grp), "r"(1) : "memory");

        // out store AFTER release — off the critical handshake path
        out[(gb * SEQ + t) * HID + c0ch + ch] = hn;
    }
}

extern "C" void kernel_launch(void* const* d_in, const int* in_sizes, int n_in,
                              void* d_out, int out_size) {
    const float* x     = (const float*)d_in[0];
    const float* h0    = (const float*)d_in[1];
    const float* c0    = (const float*)d_in[2];
    const float* Wx    = (const float*)d_in[3];
    const float* bx    = (const float*)d_in[4];
    const float* Wh    = (const float*)d_in[5];
    const float* bh    = (const float*)d_in[6];
    const float* peep  = (const float*)d_in[7];
    const float* bgate = (const float*)d_in[8];
    float* out = (float*)d_out;

    cudaFuncSetAttribute(gemm_xg_kernel, cudaFuncAttributeMaxDynamicSharedMemorySize, ASMEM);
    cudaFuncSetAttribute(lstm_kernel, cudaFuncAttributeMaxDynamicSharedMemorySize, BSMEM);

    convert_kernel<<<1024, 256>>>(x, Wx, Wh, h0);
    gemm_xg_kernel<<<dim3(32, 128), 256, ASMEM>>>();
    lstm_kernel<<<NCTA, 512, BSMEM>>>(c0, bx, bh, peep, bgate, out);
}

// round 17
// speedup vs baseline: 1.6391x; 1.0296x over previous
#include <cuda_runtime.h>
#include <cuda_fp16.h>
#include <mma.h>
#include <cstdint>

using namespace nvcuda;

#define HID   1024
#define BATCH 64
#define SEQ   256
#define NGATE 4096
#define NCTA  128
#define WHH_LD 1032
#define HA_LD 136
#define MB 32
#define CHB (32 * HA_LD)            // one chunk: 32 b x 136 halfs
#define QTR_BYTES (2 * CHB * 2)     // 17408 B: quarter of the per-bg B-image
#define HG_LD 66
#define HG_BLK (32 * HG_LD)

// lstm SMEM offsets (bytes)
#define OFF_CB  64
#define OFF_PS  320
#define OFF_CS  512
#define OFF_HG  2624
#define OFF_WHS 19520
#define OFF_HAS 151616
#define BSMEM   221248

__device__ float  g_xg[(size_t)BATCH * SEQ * NGATE];  // [b*SEQ+t][g*HID+k] fp32
__device__ __half g_xh[(size_t)BATCH * SEQ * HID];    // fp16 x
__device__ __half g_wxh[(size_t)NGATE * HID];         // fp16 Wx
__device__ __half g_whh[(size_t)NGATE * HID];         // fp16 Wh
// padded h ring: [slot][bg][kc][b][136]  (pre-padded SMEM image, bulk-copyable)
__device__ __half g_h2[4][2 * 8 * CHB];
__device__ int    g_cnt16[16];                        // [bg*8+grp]: 8 CTAs each

__device__ __forceinline__ void cp16(void* s, const void* g) {
    uint32_t sa = (uint32_t)__cvta_generic_to_shared(s);
    asm volatile("cp.async.cg.shared.global [%0], [%1], 16;\n" :: "r"(sa), "l"(g));
}
__device__ __forceinline__ void cp_commit() { asm volatile("cp.async.commit_group;\n"); }
template<int N> __device__ __forceinline__ void cp_wait() {
    asm volatile("cp.async.wait_group %0;\n" :: "n"(N));
}
__device__ __forceinline__ float sigm(float x) { return 1.0f / (1.0f + __expf(-x)); }
__device__ __forceinline__ int ld_relaxed(const int* p) {
    int v;
    asm volatile("ld.relaxed.gpu.global.s32 %0, [%1];" : "=r"(v) : "l"(p) : "memory");
    return v;
}
__device__ __forceinline__ void mbar_init(uint32_t mbar, uint32_t cnt) {
    asm volatile("mbarrier.init.shared.b64 [%0], %1;" :: "r"(mbar), "r"(cnt) : "memory");
}
__device__ __forceinline__ void mbar_expect_tx(uint32_t mbar, uint32_t tx) {
    asm volatile("mbarrier.arrive.expect_tx.shared.b64 _, [%0], %1;" :: "r"(mbar), "r"(tx) : "memory");
}
__device__ __forceinline__ void mbar_wait(uint32_t mbar, uint32_t parity) {
    asm volatile(
        "{\n\t.reg .pred P;\n"
        "WAIT_%=:\n\t"
        "mbarrier.try_wait.parity.acquire.cta.shared::cta.b64 P, [%0], %1, 0x989680;\n\t"
        "@P bra WAIT_DONE_%=;\n\t"
        "bra WAIT_%=;\n"
        "WAIT_DONE_%=:\n\t}"
        :: "r"(mbar), "r"(parity) : "memory");
}
__device__ __forceinline__ void bulk_ld(uint32_t dst, const void* src, uint32_t bytes, uint32_t mbar) {
    asm volatile(
        "cp.async.bulk.shared::cluster.global.mbarrier::complete_tx::bytes [%0], [%1], %2, [%3];"
        :: "r"(dst), "l"(src), "r"(bytes), "r"(mbar) : "memory");
}

// ------------------------------------------------------------------ convert to fp16
__global__ void convert_kernel(const float* __restrict__ x,
                               const float* __restrict__ Wx,
                               const float* __restrict__ Wh,
                               const float* __restrict__ h0) {
    size_t idx = (size_t)blockIdx.x * blockDim.x + threadIdx.x;
    size_t tot = (size_t)gridDim.x * blockDim.x;
    for (size_t i = idx; i < (size_t)BATCH * SEQ * HID; i += tot) g_xh[i]  = __float2half(x[i]);
    for (size_t i = idx; i < (size_t)NGATE * HID; i += tot)       g_wxh[i] = __float2half(Wx[i]);
    for (size_t i = idx; i < (size_t)NGATE * HID; i += tot)       g_whh[i] = __float2half(Wh[i]);
    for (size_t i = idx; i < (size_t)BATCH * HID; i += tot) {
        int b = (int)(i >> 10), k = (int)(i & 1023);
        g_h2[0][((b >> 5) * 8 + (k >> 7)) * CHB + (b & 31) * HA_LD + (k & 127)] = __float2half(h0[i]);
    }
}

// ------------------------------------------------------------------ phase A (fp16 wmma, 128x128, BK=64)
#define BK 64
#define A_LD 72
#define ASMEM (2 * 3 * 128 * A_LD * 2)   // 110592
__global__ void __launch_bounds__(256, 2) gemm_xg_kernel() {
    extern __shared__ __half smh[];
    __half* As = smh;                     // [3][128][72]
    __half* Bs = smh + 3 * 128 * A_LD;    // [3][128][72]
    const int tid = threadIdx.x;
    const int wid = tid >> 5;
    const int wm = wid & 3, wn = wid >> 2;
    const int tm = blockIdx.y * 128;
    const int tn = blockIdx.x * 128;

    if (blockIdx.x == 0 && blockIdx.y == 0 && tid < 16) g_cnt16[tid] = 8;  // h(0) published

    wmma::fragment<wmma::accumulator, 16, 16, 16, float> acc[2][4];
    #pragma unroll
    for (int i = 0; i < 2; i++)
        #pragma unroll
        for (int j = 0; j < 4; j++) wmma::fill_fragment(acc[i][j], 0.0f);

    auto issue = [&](int kt) {
        int st = kt % 3;
        int kk = kt * BK;
        __half* a = As + st * 128 * A_LD;
        __half* b = Bs + st * 128 * A_LD;
        #pragma unroll
        for (int i = 0; i < 8; i++) {
            int li = tid + i * 256;          // 0..2047
            int half_sel = li >> 10;
            int lj = li & 1023;
            int r = lj >> 3, sg = lj & 7;    // 128 rows x 8 segs
            if (half_sel == 0)
                cp16(a + r * A_LD + sg * 8, g_xh  + (size_t)(tm + r) * HID + kk + sg * 8);
            else
                cp16(b + r * A_LD + sg * 8, g_wxh + (size_t)(tn + r) * HID + kk + sg * 8);
        }
    };
    issue(0); cp_commit();
    issue(1); cp_commit();

    for (int kt = 0; kt < HID / BK; kt++) {
        cp_wait<1>();
        __syncthreads();
        const int st = kt % 3;
        const __half* a = As + st * 128 * A_LD;
        const __half* b = Bs + st * 128 * A_LD;
        #pragma unroll
        for (int ks = 0; ks < 4; ks++) {
            wmma::fragment<wmma::matrix_a, 16, 16, 16, __half, wmma::row_major> af[2];
            wmma::fragment<wmma::matrix_b, 16, 16, 16, __half, wmma::col_major> bf[4];
            #pragma unroll
            for (int i = 0; i < 2; i++)
                wmma::load_matrix_sync(af[i], a + (wm * 32 + i * 16) * A_LD + ks * 16, A_LD);
            #pragma unroll
            for (int j = 0; j < 4; j++)
                wmma::load_matrix_sync(bf[j], b + (wn * 64 + j * 16) * A_LD + ks * 16, A_LD);
            #pragma unroll
            for (int i = 0; i < 2; i++)
                #pragma unroll
                for (int j = 0; j < 4; j++)
                    wmma::mma_sync(acc[i][j], af[i], bf[j], acc[i][j]);
        }
        if (kt + 2 < HID / BK) issue(kt + 2);
        cp_commit();
    }
    #pragma unroll
    for (int i = 0; i < 2; i++)
        #pragma unroll
        for (int j = 0; j < 4; j++) {
            size_t r = tm + wm * 32 + i * 16;
            size_t n = tn + wn * 64 + j * 16;
            wmma::store_matrix_sync(g_xg + r * NGATE + n, acc[i][j], NGATE, wmma::mem_row_major);
        }
}

// ------------------------------------------------------------------ phase B
// 2 bg x 64 channel blocks. QUARTER wavefront: poller tid0 handles quarters 0,1
// (groups 0-1 / 2-3) sequentially; poller tid128 handles quarters 2,3.
// Consumers: warp stream sk waits quarter 2sk, computes 16 frags, waits 2sk+1, computes 16.
__global__ void __launch_bounds__(512, 1) lstm_kernel(const float* __restrict__ c0,
                                                      const float* __restrict__ bx,
                                                      const float* __restrict__ bh,
                                                      const float* __restrict__ peep,
                                                      const float* __restrict__ bgate,
                                                      float* __restrict__ out) {
    extern __shared__ char smc[];
    float*  cb  = (float*)(smc + OFF_CB);         // 64
    float*  ps  = (float*)(smc + OFF_PS);         // 48
    float*  cS  = (float*)(smc + OFF_CS);         // [16][33]
    float*  hgS = (float*)(smc + OFF_HG);         // [2][32][66]
    __half* Whs = (__half*)(smc + OFF_WHS);       // [64][1032]
    __half* hAs = (__half*)(smc + OFF_HAS);       // [8][32][136] full B-image
    const uint32_t sbase = (uint32_t)__cvta_generic_to_shared(smc);
    const uint32_t hAs_u = sbase + OFF_HAS;

    const int tid = threadIdx.x;
    const int wid = tid >> 5;
    const int rt  = wid & 3;                      // Wh row tile 0..3
    const int sk  = (wid >> 2) & 1;               // K-stream 0..1
    const int bt  = wid >> 3;                     // batch tile 0..1
    const int j   = blockIdx.x & 63;              // channel block
    const int bg  = blockIdx.x >> 6;              // batch group
    const int c0ch = j * 16;
    const int grp = bg * 8 + (j >> 3);

    // one-time: stage this CTA's fp16 Wh slice (64 rows x 1024)
    #pragma unroll
    for (int i = 0; i < 16; i++) {
        int li = tid + i * 512;
        int n = li >> 7, sg = li & 127;
        int g = n >> 4, ch = n & 15;
        cp16(Whs + n * WHH_LD + sg * 8,
             g_whh + ((size_t)(g * HID + c0ch + ch)) * HID + sg * 8);
    }
    cp_commit();
    if (tid < 64) {
        int g = tid >> 4, ch = tid & 15;
        cb[tid] = bx[g * HID + c0ch + ch] + bh[g * HID + c0ch + ch] + bgate[g * HID + c0ch + ch];
    }
    if (tid < 48) ps[tid] = peep[(tid >> 4) * HID + c0ch + (tid & 15)];
    {
        int b = tid >> 4, ch = tid & 15;
        cS[ch * 33 + b] = c0[(size_t)(bg * MB + b) * HID + c0ch + ch];
    }
    if (tid == 0) {
        mbar_init(sbase, 1);         // quarter 0
        mbar_init(sbase + 8, 1);     // quarter 1
        mbar_init(sbase + 16, 1);    // quarter 2
        mbar_init(sbase + 24, 1);    // quarter 3
        asm volatile("fence.proxy.async.shared::cta;" ::: "memory");
    }
    cp_wait<0>();
    __syncthreads();

    const int b  = tid >> 4;
    const int ch = tid & 15;
    const size_t gb = (size_t)(bg * MB + b);
    const bool is_poller = (tid == 0) || (tid == 128);

    for (int t = 0; t < SEQ; t++) {
        // prefetch this step's input-gate preactivations (independent of h_t)
        const float* xr = g_xg + (gb * SEQ + t) * NGATE + c0ch + ch;
        float xi0 = __ldg(xr);
        float xi1 = __ldg(xr + HID);
        float xi2 = __ldg(xr + 2 * HID);
        float xi3 = __ldg(xr + 3 * HID);

        if (is_poller) {
            const int base_q = (tid == 128) ? 2 : 0;
            const int need = 8 * (t + 1);
            const __half* hsrc = g_h2[t & 3] + (size_t)bg * 8 * CHB;
            #pragma unroll
            for (int qq = 0; qq < 2; qq++) {
                const int q = base_q + qq;
                const int* cnt = g_cnt16 + bg * 8 + q * 2;
                while (true) {
                    int v0 = ld_relaxed(cnt);
                    int v1 = ld_relaxed(cnt + 1);
                    if (v0 >= need && v1 >= need) break;
                }
                asm volatile("fence.acq_rel.gpu;" ::: "memory");
                asm volatile("fence.proxy.async;" ::: "memory");
                mbar_expect_tx(sbase + q * 8, QTR_BYTES);
                bulk_ld(hAs_u + q * QTR_BYTES, hsrc + (size_t)q * 2 * CHB, QTR_BYTES, sbase + q * 8);
            }
        }

        wmma::fragment<wmma::accumulator, 16, 16, 16, float> acc0, acc1;
        wmma::fill_fragment(acc0, 0.0f);
        wmma::fill_fragment(acc1, 0.0f);
        const __half* bbase = Whs + (rt * 16) * WHH_LD;

        // first quarter of this K-stream (chunks 2sk*2 .. +1)
        mbar_wait(sbase + (sk * 2) * 8, t & 1);
        #pragma unroll 8
        for (int f = sk * 32; f < sk * 32 + 16; f += 2) {
            const __half* a0 = hAs + (f >> 3) * CHB + (bt * 16) * HA_LD + (f & 7) * 16;
            const __half* a1 = hAs + ((f + 1) >> 3) * CHB + (bt * 16) * HA_LD + ((f + 1) & 7) * 16;
            wmma::fragment<wmma::matrix_a, 16, 16, 16, __half, wmma::row_major> af0, af1;
            wmma::fragment<wmma::matrix_b, 16, 16, 16, __half, wmma::col_major> bf0, bf1;
            wmma::load_matrix_sync(af0, a0, HA_LD);
            wmma::load_matrix_sync(bf0, bbase + f * 16, WHH_LD);
            wmma::load_matrix_sync(af1, a1, HA_LD);
            wmma::load_matrix_sync(bf1, bbase + (f + 1) * 16, WHH_LD);
            wmma::mma_sync(acc0, af0, bf0, acc0);
            wmma::mma_sync(acc1, af1, bf1, acc1);
        }
        // second quarter of this K-stream
        mbar_wait(sbase + (sk * 2 + 1) * 8, t & 1);
        #pragma unroll 8
        for (int f = sk * 32 + 16; f < sk * 32 + 32; f += 2) {
            const __half* a0 = hAs + (f >> 3) * CHB + (bt * 16) * HA_LD + (f & 7) * 16;
            const __half* a1 = hAs + ((f + 1) >> 3) * CHB + (bt * 16) * HA_LD + ((f + 1) & 7) * 16;
            wmma::fragment<wmma::matrix_a, 16, 16, 16, __half, wmma::row_major> af0, af1;
            wmma::fragment<wmma::matrix_b, 16, 16, 16, __half, wmma::col_major> bf0, bf1;
            wmma::load_matrix_sync(af0, a0, HA_LD);
            wmma::load_matrix_sync(bf0, bbase + f * 16, WHH_LD);
            wmma::load_matrix_sync(af1, a1, HA_LD);
            wmma::load_matrix_sync(bf1, bbase + (f + 1) * 16, WHH_LD);
            wmma::mma_sync(acc0, af0, bf0, acc0);
            wmma::mma_sync(acc1, af1, bf1, acc1);
        }
        #pragma unroll
        for (int e = 0; e < acc0.num_elements; e++) acc0.x[e] += acc1.x[e];
        wmma::store_matrix_sync(hgS + sk * HG_BLK + (bt * 16) * HG_LD + rt * 16,
                                acc0, HG_LD, wmma::mem_row_major);
        __syncthreads();

        // epilogue: sum 2 K-stream partials, gates; h written into ring image
        float c = cS[ch * 33 + b];
        const float* hb = hgS + b * HG_LD;
        float hv0 = hb[ch]      + hb[HG_BLK + ch];
        float hv1 = hb[16 + ch] + hb[HG_BLK + 16 + ch];
        float hv2 = hb[32 + ch] + hb[HG_BLK + 32 + ch];
        float hv3 = hb[48 + ch] + hb[HG_BLK + 48 + ch];
        float pi = xi0 + hv0 + ps[ch]      * c + cb[ch];
        float pf = xi1 + hv1 + ps[16 + ch] * c + cb[16 + ch];
        float pc = xi2 + hv2                   + cb[32 + ch];
        float po = xi3 + hv3                   + cb[48 + ch];
        float cn = sigm(pf) * c + sigm(pi) + tanhf(pc);
        float hn = sigm(po + ps[32 + ch] * cn) * tanhf(cn);
        cS[ch * 33 + b] = cn;
        g_h2[(t + 1) & 3][((size_t)bg * 8 + (j >> 3)) * CHB + b * HA_LD + (j & 7) * 16 + ch]
            = __float2half(hn);
        __syncthreads();                    // all h stores happen-before the release
        if (tid == 0)
            asm volatile("red.release.gpu.global.add.s32 [%0], %1;"
                         :: "l"(g_cnt16 + grp), "r"(1) : "memory");

        // out store AFTER release — off the critical handshake path
        out[(gb * SEQ + t) * HID + c0ch + ch] = hn;
    }
}

extern "C" void kernel_launch(void* const* d_in, const int* in_sizes, int n_in,
                              void* d_out, int out_size) {
    const float* x     = (const float*)d_in[0];
    const float* h0    = (const float*)d_in[1];
    const float* c0    = (const float*)d_in[2];
    const float* Wx    = (const float*)d_in[3];
    const float* bx    = (const float*)d_in[4];
    const float* Wh    = (const float*)d_in[5];
    const float* bh    = (const float*)d_in[6];
    const float* peep  = (const float*)d_in[7];
    const float* bgate = (const float*)d_in[8];
    float* out = (float*)d_out;

    cudaFuncSetAttribute(gemm_xg_kernel, cudaFuncAttributeMaxDynamicSharedMemorySize, ASMEM);
    cudaFuncSetAttribute(lstm_kernel, cudaFuncAttributeMaxDynamicSharedMemorySize, BSMEM);

    convert_kernel<<<1024, 256>>>(x, Wx, Wh, h0);
    gemm_xg_kernel<<<dim3(32, 128), 256, ASMEM>>>();
    lstm_kernel<<<NCTA, 512, BSMEM>>>(c0, bx, bh, peep, bgate, out);
}